// round 3
// baseline (speedup 1.0000x reference)
#include <cuda_runtime.h>
#include <cuda_bf16.h>
#include <cstdint>

// LSTM: B=4096, T=2048, I=3, H=32.  out = h_final [B, H] fp32.
// Inputs (metadata order): x [B,T,I], W_ih [4H,I], W_hh [4H,H], b_ih [4H], b_hh [4H]
//
// Mapping: 1 warp per batch row. lane = hidden index (H==32).
// Lane owns h[lane], c[lane]; computes gate rows lane, lane+32, lane+64, lane+96.
// W_hh kept entirely in registers, packed in k-pairs for fma.rn.f32x2 (Blackwell
// dual-fp32 FMA): acc halves accumulate even/odd k, one horizontal add per gate.
// x staging is software-pipelined: chunk n+1's 3 coalesced loads issue before
// chunk n's 32 inner steps, hiding the ~577-cycle DRAM latency.

#define BB 4096
#define TT 2048
#define II 3
#define HH 32

typedef unsigned long long u64;

__device__ __forceinline__ u64 pack2(float x, float y) {
    u64 r; asm("mov.b64 %0, {%1, %2};" : "=l"(r) : "f"(x), "f"(y)); return r;
}
__device__ __forceinline__ void unpack2(u64 v, float& a, float& b) {
    asm("mov.b64 {%0, %1}, %2;" : "=f"(a), "=f"(b) : "l"(v));
}
// Blackwell packed dual-fp32 fma: d.lo = a.lo*b.lo + c.lo ; d.hi = a.hi*b.hi + c.hi
__device__ __forceinline__ u64 ffma2(u64 a, u64 b, u64 c) {
    u64 d; asm("fma.rn.f32x2 %0, %1, %2, %3;" : "=l"(d) : "l"(a), "l"(b), "l"(c));
    return d;
}

__device__ __forceinline__ float ex2a(float x) {
    float r; asm("ex2.approx.ftz.f32 %0, %1;" : "=f"(r) : "f"(x)); return r;
}
__device__ __forceinline__ float rcpa(float x) {
    float r; asm("rcp.approx.ftz.f32 %0, %1;" : "=f"(r) : "f"(x)); return r;
}
// sigmoid(x) = 1 / (1 + 2^(-x*log2 e)).  Safe at both extremes:
// x->-inf: e->inf, rcp(inf)=0.  x->+inf: e->0, rcp(1)=1.
__device__ __forceinline__ float sigm(float x) {
    return rcpa(1.0f + ex2a(-1.4426950408889634f * x));
}
// tanh(x) = sign(x) * (1 - e^{-2|x|}) / (1 + e^{-2|x|}).
// Evaluated on |x| so e ∈ (0,1] and no inf/NaN path exists for any input.
// fabsf/copysignf are LOP3 (alu pipe) — free w.r.t. the binding fma pipe.
__device__ __forceinline__ float tanh_f(float x) {
    float ax = fabsf(x);
    float e = ex2a(-2.8853900817779268f * ax);
    float r = (1.0f - e) * rcpa(1.0f + e);
    return copysignf(r, x);
}

__global__ void __launch_bounds__(128)
lstm_warp_per_batch(const float* __restrict__ x,
                    const float* __restrict__ W_ih,
                    const float* __restrict__ W_hh,
                    const float* __restrict__ b_ih,
                    const float* __restrict__ b_hh,
                    float* __restrict__ out)
{
    const int lane = threadIdx.x & 31;
    const int b = blockIdx.x * (blockDim.x >> 5) + (threadIdx.x >> 5);
    if (b >= BB) return;

    const int ri = lane;          // i gate row
    const int rf = lane + 32;     // f
    const int rg = lane + 64;     // g
    const int ro = lane + 96;     // o

    // ---- W_hh rows into registers, packed along k in pairs ----
    u64 WI[16], WF[16], WG[16], WO[16];
    {
        const float2* wi = reinterpret_cast<const float2*>(W_hh + ri * HH);
        const float2* wf = reinterpret_cast<const float2*>(W_hh + rf * HH);
        const float2* wg = reinterpret_cast<const float2*>(W_hh + rg * HH);
        const float2* wo = reinterpret_cast<const float2*>(W_hh + ro * HH);
#pragma unroll
        for (int k = 0; k < 16; ++k) {
            float2 a;
            a = wi[k]; WI[k] = pack2(a.x, a.y);
            a = wf[k]; WF[k] = pack2(a.x, a.y);
            a = wg[k]; WG[k] = pack2(a.x, a.y);
            a = wo[k]; WO[k] = pack2(a.x, a.y);
        }
    }

    // ---- W_ih rows (I=3): packed (w0,w1) and (w2,0) per gate ----
    const u64 XI0 = pack2(W_ih[ri*II + 0], W_ih[ri*II + 1]);
    const u64 XI2 = pack2(W_ih[ri*II + 2], 0.0f);
    const u64 XF0 = pack2(W_ih[rf*II + 0], W_ih[rf*II + 1]);
    const u64 XF2 = pack2(W_ih[rf*II + 2], 0.0f);
    const u64 XG0 = pack2(W_ih[rg*II + 0], W_ih[rg*II + 1]);
    const u64 XG2 = pack2(W_ih[rg*II + 2], 0.0f);
    const u64 XO0 = pack2(W_ih[ro*II + 0], W_ih[ro*II + 1]);
    const u64 XO2 = pack2(W_ih[ro*II + 2], 0.0f);

    // ---- biases (b_ih + b_hh), folded into accumulator init (lo half) ----
    const u64 BI = pack2(b_ih[ri] + b_hh[ri], 0.0f);
    const u64 BF = pack2(b_ih[rf] + b_hh[rf], 0.0f);
    const u64 BG = pack2(b_ih[rg] + b_hh[rg], 0.0f);
    const u64 BO = pack2(b_ih[ro] + b_hh[ro], 0.0f);

    const float* xb = x + (size_t)b * (TT * II);

    float h = 0.0f, c = 0.0f;
    const unsigned FULL = 0xffffffffu;

    // ---- software-pipelined x staging: prefetch chunk 0 ----
    float xA = xb[lane];
    float xB = xb[32 + lane];
    float xC = xb[64 + lane];

    for (int t0 = 0; t0 < TT; t0 += 32) {
        // Consume the prefetched chunk; issue next chunk's loads now so their
        // ~577-cycle latency hides under the 32 inner steps.
        float cA = xA, cB = xB, cC = xC;
        if (t0 + 32 < TT) {
            const float* xn = xb + (t0 + 32) * II;
            xA = xn[lane];
            xB = xn[32 + lane];
            xC = xn[64 + lane];
        }

#pragma unroll
        for (int s = 0; s < 32; ++s) {
            const int j0 = 3 * s, j1 = j0 + 1, j2 = j0 + 2;
            // register select constant-folds after full unroll
            float x0 = __shfl_sync(FULL, (j0 < 32) ? cA : ((j0 < 64) ? cB : cC), j0 & 31);
            float x1 = __shfl_sync(FULL, (j1 < 32) ? cA : ((j1 < 64) ? cB : cC), j1 & 31);
            float x2 = __shfl_sync(FULL, (j2 < 32) ? cA : ((j2 < 64) ? cB : cC), j2 & 31);

            u64 xp01 = pack2(x0, x1);
            u64 xp2  = pack2(x2, 0.0f);

            u64 aI = ffma2(XI0, xp01, BI); aI = ffma2(XI2, xp2, aI);
            u64 aF = ffma2(XF0, xp01, BF); aF = ffma2(XF2, xp2, aF);
            u64 aG = ffma2(XG0, xp01, BG); aG = ffma2(XG2, xp2, aG);
            u64 aO = ffma2(XO0, xp01, BO); aO = ffma2(XO2, xp2, aO);

            // recurrent matvec: 32 shuffles, 64 FFMA2 (k packed in pairs)
#pragma unroll
            for (int k = 0; k < 16; ++k) {
                float ha = __shfl_sync(FULL, h, 2 * k);
                float hb = __shfl_sync(FULL, h, 2 * k + 1);
                u64 hp = pack2(ha, hb);
                aI = ffma2(WI[k], hp, aI);
                aF = ffma2(WF[k], hp, aF);
                aG = ffma2(WG[k], hp, aG);
                aO = ffma2(WO[k], hp, aO);
            }

            float l0, h0, l1, h1, l2, h2, l3, h3;
            unpack2(aI, l0, h0);
            unpack2(aF, l1, h1);
            unpack2(aG, l2, h2);
            unpack2(aO, l3, h3);
            float gi = l0 + h0;
            float gf = l1 + h1;
            float gg = l2 + h2;
            float go = l3 + h3;

            float ig = sigm(gi);
            float fg = sigm(gf);
            float gv = tanh_f(gg);
            float og = sigm(go);

            c = fmaf(fg, c, ig * gv);
            h = og * tanh_f(c);
        }
    }

    out[b * HH + lane] = h;
}

extern "C" void kernel_launch(void* const* d_in, const int* in_sizes, int n_in,
                              void* d_out, int out_size) {
    const float* x    = (const float*)d_in[0];
    const float* W_ih = (const float*)d_in[1];
    const float* W_hh = (const float*)d_in[2];
    const float* b_ih = (const float*)d_in[3];
    const float* b_hh = (const float*)d_in[4];
    float* out = (float*)d_out;

    // 1 warp per batch row: 4096 warps, 128 threads/block -> 1024 blocks
    dim3 block(128);
    dim3 grid(BB / 4);
    lstm_warp_per_batch<<<grid, block>>>(x, W_ih, W_hh, b_ih, b_hh, out);
}

// round 4
// speedup vs baseline: 1.3048x; 1.3048x over previous
#include <cuda_runtime.h>
#include <cuda_bf16.h>
#include <cstdint>

// LSTM: B=4096, T=2048, I=3, H=32.  out = h_final [B, H] fp32.
// Inputs: x [B,T,I], W_ih [4H,I], W_hh [4H,H], b_ih [4H], b_hh [4H]
//
// Mapping: 1 warp per 2 batch rows (ILP: 2 independent recurrence chains/warp,
// 4 per SMSP at 2 warps/SMSP). lane = hidden index (H==32). Lane owns h[lane],
// c[lane] per row; computes gate rows lane, lane+32, lane+64, lane+96.
// W_hh register-resident, packed in k-pairs for fma.rn.f32x2; weight registers
// are shared across the 2 rows. No shuffles: h redistributed via per-warp smem
// double buffer (broadcast LDS.64 gives (h[2k],h[2k+1]) as an aligned pair),
// x via padded smem (one broadcast LDS.128 per row-step).

#define BB 4096
#define TT 2048
#define II 3
#define HH 32
#define WPB 4   // warps per block

typedef unsigned long long u64;

__device__ __forceinline__ u64 pack2(float x, float y) {
    u64 r; asm("mov.b64 %0, {%1, %2};" : "=l"(r) : "f"(x), "f"(y)); return r;
}
__device__ __forceinline__ void unpack2(u64 v, float& a, float& b) {
    asm("mov.b64 {%0, %1}, %2;" : "=f"(a), "=f"(b) : "l"(v));
}
// Blackwell packed dual-fp32 fma: d.lo = a.lo*b.lo + c.lo ; d.hi = a.hi*b.hi + c.hi
__device__ __forceinline__ u64 ffma2(u64 a, u64 b, u64 c) {
    u64 d; asm("fma.rn.f32x2 %0, %1, %2, %3;" : "=l"(d) : "l"(a), "l"(b), "l"(c));
    return d;
}

__device__ __forceinline__ float ex2a(float x) {
    float r; asm("ex2.approx.ftz.f32 %0, %1;" : "=f"(r) : "f"(x)); return r;
}
__device__ __forceinline__ float rcpa(float x) {
    float r; asm("rcp.approx.ftz.f32 %0, %1;" : "=f"(r) : "f"(x)); return r;
}
// sigmoid(x) = 1 / (1 + 2^(-x*log2 e)); safe at both extremes.
__device__ __forceinline__ float sigm(float x) {
    return rcpa(1.0f + ex2a(-1.4426950408889634f * x));
}
// tanh(x) = sign(x) * (1 - e^{-2|x|}) / (1 + e^{-2|x|}); no inf/NaN path.
__device__ __forceinline__ float tanh_f(float x) {
    float ax = fabsf(x);
    float e = ex2a(-2.8853900817779268f * ax);
    float r = (1.0f - e) * rcpa(1.0f + e);
    return copysignf(r, x);
}

__global__ void __launch_bounds__(32 * WPB)
lstm_warp2rows(const float* __restrict__ x,
               const float* __restrict__ W_ih,
               const float* __restrict__ W_hh,
               const float* __restrict__ b_ih,
               const float* __restrict__ b_hh,
               float* __restrict__ out)
{
    // [warp][parity][row][hidden]
    __shared__ float hbuf[WPB][2][2][HH];
    // [warp][row][step][4]  (x0,x1,x2,pad) -> one LDS.128 per row-step
    __shared__ float xbuf[WPB][2][32][4];

    const int lane = threadIdx.x & 31;
    const int wib  = threadIdx.x >> 5;
    const int gw   = blockIdx.x * WPB + wib;
    const int b0   = gw * 2;
    if (b0 >= BB) return;

    const int ri = lane, rf = lane + 32, rg = lane + 64, ro = lane + 96;

    // ---- W_hh rows into registers, packed along k in pairs (shared by both rows) ----
    u64 WI[16], WF[16], WG[16], WO[16];
    {
        const float2* wi = reinterpret_cast<const float2*>(W_hh + ri * HH);
        const float2* wf = reinterpret_cast<const float2*>(W_hh + rf * HH);
        const float2* wg = reinterpret_cast<const float2*>(W_hh + rg * HH);
        const float2* wo = reinterpret_cast<const float2*>(W_hh + ro * HH);
#pragma unroll
        for (int k = 0; k < 16; ++k) {
            float2 a;
            a = wi[k]; WI[k] = pack2(a.x, a.y);
            a = wf[k]; WF[k] = pack2(a.x, a.y);
            a = wg[k]; WG[k] = pack2(a.x, a.y);
            a = wo[k]; WO[k] = pack2(a.x, a.y);
        }
    }

    // ---- W_ih rows (I=3): packed (w0,w1) and (w2,0) per gate ----
    const u64 XI0 = pack2(W_ih[ri*II + 0], W_ih[ri*II + 1]);
    const u64 XI2 = pack2(W_ih[ri*II + 2], 0.0f);
    const u64 XF0 = pack2(W_ih[rf*II + 0], W_ih[rf*II + 1]);
    const u64 XF2 = pack2(W_ih[rf*II + 2], 0.0f);
    const u64 XG0 = pack2(W_ih[rg*II + 0], W_ih[rg*II + 1]);
    const u64 XG2 = pack2(W_ih[rg*II + 2], 0.0f);
    const u64 XO0 = pack2(W_ih[ro*II + 0], W_ih[ro*II + 1]);
    const u64 XO2 = pack2(W_ih[ro*II + 2], 0.0f);

    // ---- biases (b_ih + b_hh) folded into accumulator init (lo half) ----
    const u64 BI = pack2(b_ih[ri] + b_hh[ri], 0.0f);
    const u64 BF = pack2(b_ih[rf] + b_hh[rf], 0.0f);
    const u64 BG = pack2(b_ih[rg] + b_hh[rg], 0.0f);
    const u64 BO = pack2(b_ih[ro] + b_hh[ro], 0.0f);

    const float* xb0 = x + (size_t)(b0 + 0) * (TT * II);
    const float* xb1 = x + (size_t)(b0 + 1) * (TT * II);

    float h0 = 0.0f, c0 = 0.0f, h1 = 0.0f, c1 = 0.0f;

    // init h buffer (parity 0) with h_{-1} = 0
    hbuf[wib][0][0][lane] = 0.0f;
    hbuf[wib][0][1][lane] = 0.0f;

    // ---- prefetch chunk 0 x into registers (coalesced) ----
    float pA0 = xb0[lane], pB0 = xb0[32 + lane], pC0 = xb0[64 + lane];
    float pA1 = xb1[lane], pB1 = xb1[32 + lane], pC1 = xb1[64 + lane];

    // remap targets for staging: flat index j -> (step j/3, comp j%3)
    const int tA = lane / 3,        cA = lane - 3 * tA;
    const int tB = (32 + lane) / 3, cB = (32 + lane) - 3 * tB;
    const int tC = (64 + lane) / 3, cC = (64 + lane) - 3 * tC;

    int p = 0;
    __syncwarp();

    for (int t0 = 0; t0 < TT; t0 += 32) {
        // stage current chunk's x into smem (remapped to 4-float stride)
        float* xr0 = &xbuf[wib][0][0][0];
        float* xr1 = &xbuf[wib][1][0][0];
        xr0[4 * tA + cA] = pA0;  xr0[4 * tB + cB] = pB0;  xr0[4 * tC + cC] = pC0;
        xr1[4 * tA + cA] = pA1;  xr1[4 * tB + cB] = pB1;  xr1[4 * tC + cC] = pC1;

        // prefetch next chunk
        if (t0 + 32 < TT) {
            const float* xn0 = xb0 + (t0 + 32) * II;
            const float* xn1 = xb1 + (t0 + 32) * II;
            pA0 = xn0[lane]; pB0 = xn0[32 + lane]; pC0 = xn0[64 + lane];
            pA1 = xn1[lane]; pB1 = xn1[32 + lane]; pC1 = xn1[64 + lane];
        }
        __syncwarp();   // xbuf visible before step 0 reads it

#pragma unroll 4
        for (int s = 0; s < 32; ++s) {
            // x values: one broadcast LDS.128 per row
            float4 xv0 = *reinterpret_cast<const float4*>(&xbuf[wib][0][s][0]);
            float4 xv1 = *reinterpret_cast<const float4*>(&xbuf[wib][1][s][0]);

            u64 xa0 = pack2(xv0.x, xv0.y), xb0p = pack2(xv0.z, 0.0f);
            u64 xa1 = pack2(xv1.x, xv1.y), xb1p = pack2(xv1.z, 0.0f);

            u64 aI0 = ffma2(XI0, xa0, BI); aI0 = ffma2(XI2, xb0p, aI0);
            u64 aF0 = ffma2(XF0, xa0, BF); aF0 = ffma2(XF2, xb0p, aF0);
            u64 aG0 = ffma2(XG0, xa0, BG); aG0 = ffma2(XG2, xb0p, aG0);
            u64 aO0 = ffma2(XO0, xa0, BO); aO0 = ffma2(XO2, xb0p, aO0);

            u64 aI1 = ffma2(XI0, xa1, BI); aI1 = ffma2(XI2, xb1p, aI1);
            u64 aF1 = ffma2(XF0, xa1, BF); aF1 = ffma2(XF2, xb1p, aF1);
            u64 aG1 = ffma2(XG0, xa1, BG); aG1 = ffma2(XG2, xb1p, aG1);
            u64 aO1 = ffma2(XO0, xa1, BO); aO1 = ffma2(XO2, xb1p, aO1);

            const float* hb0 = &hbuf[wib][p][0][0];
            const float* hb1 = &hbuf[wib][p][1][0];

            // recurrent matvec: 16 broadcast LDS.64 per row, 128 FFMA2 total
#pragma unroll
            for (int k = 0; k < 16; ++k) {
                float2 f0 = *reinterpret_cast<const float2*>(hb0 + 2 * k);
                float2 f1 = *reinterpret_cast<const float2*>(hb1 + 2 * k);
                u64 hp0 = pack2(f0.x, f0.y);
                u64 hp1 = pack2(f1.x, f1.y);
                aI0 = ffma2(WI[k], hp0, aI0);
                aF0 = ffma2(WF[k], hp0, aF0);
                aG0 = ffma2(WG[k], hp0, aG0);
                aO0 = ffma2(WO[k], hp0, aO0);
                aI1 = ffma2(WI[k], hp1, aI1);
                aF1 = ffma2(WF[k], hp1, aF1);
                aG1 = ffma2(WG[k], hp1, aG1);
                aO1 = ffma2(WO[k], hp1, aO1);
            }

            // row 0 epilogue
            {
                float l0, hh0, l1, hh1, l2, hh2, l3, hh3;
                unpack2(aI0, l0, hh0); unpack2(aF0, l1, hh1);
                unpack2(aG0, l2, hh2); unpack2(aO0, l3, hh3);
                float gi = l0 + hh0, gf = l1 + hh1, gg = l2 + hh2, go = l3 + hh3;
                float ig = sigm(gi), fg = sigm(gf), gv = tanh_f(gg), og = sigm(go);
                c0 = fmaf(fg, c0, ig * gv);
                h0 = og * tanh_f(c0);
            }
            // row 1 epilogue
            {
                float l0, hh0, l1, hh1, l2, hh2, l3, hh3;
                unpack2(aI1, l0, hh0); unpack2(aF1, l1, hh1);
                unpack2(aG1, l2, hh2); unpack2(aO1, l3, hh3);
                float gi = l0 + hh0, gf = l1 + hh1, gg = l2 + hh2, go = l3 + hh3;
                float ig = sigm(gi), fg = sigm(gf), gv = tanh_f(gg), og = sigm(go);
                c1 = fmaf(fg, c1, ig * gv);
                h1 = og * tanh_f(c1);
            }

            // publish h for next step into the other parity buffer
            hbuf[wib][p ^ 1][0][lane] = h0;
            hbuf[wib][p ^ 1][1][lane] = h1;
            __syncwarp();
            p ^= 1;
        }
    }

    out[(b0 + 0) * HH + lane] = h0;
    out[(b0 + 1) * HH + lane] = h1;
}

extern "C" void kernel_launch(void* const* d_in, const int* in_sizes, int n_in,
                              void* d_out, int out_size) {
    const float* x    = (const float*)d_in[0];
    const float* W_ih = (const float*)d_in[1];
    const float* W_hh = (const float*)d_in[2];
    const float* b_ih = (const float*)d_in[3];
    const float* b_hh = (const float*)d_in[4];
    float* out = (float*)d_out;

    // 2 rows per warp: 2048 warps, 4 warps/block -> 512 blocks
    dim3 block(32 * WPB);
    dim3 grid((BB / 2) / WPB);
    lstm_warp2rows<<<grid, block>>>(x, W_ih, W_hh, b_ih, b_hh, out);
}